// round 4
// baseline (speedup 1.0000x reference)
#include <cuda_runtime.h>
#include <math.h>

// ---------------------------------------------------------------------------
// QuanvolutionEnhanced — fp32 SIMT implementation, 3 kernels.
//   A: per-sample 36-channel 14x14 feature map (ds-conv pooled + quantum patches)
//   B: 36->128 3x3 conv + bias + ReLU + 2x2 avgpool  (dominant: 16.6 GFLOP)
//   C: classifier heads (10 logits + 1 aux) via warp-per-row dot products
// ---------------------------------------------------------------------------

#define NB 1024

__device__ float g_fmap[NB * 36 * 196];   // (b, c, 14*14)
__device__ float g_pool[NB * 128 * 49];   // (b, c, 7*7)  == flattened features

// ---------------------------------------------------------------------------
// Kernel A
// ---------------------------------------------------------------------------
__global__ __launch_bounds__(256) void featA(
    const float* __restrict__ x,     // (B,1,28,28)
    const float* __restrict__ dw_w,  // (1,1,3,3)
    const float* __restrict__ pw_w,  // (32,1,1,1)
    const float* __restrict__ pw_b,  // (32)
    const float* __restrict__ U)     // (16,16)
{
    __shared__ float xs[30 * 30];    // zero-padded input
    __shared__ float Us[256];
    __shared__ float dws[9];
    __shared__ float pwws[32], pwbs[32];

    const int b = blockIdx.x;
    const int tid = threadIdx.x;

    for (int idx = tid; idx < 900; idx += 256) xs[idx] = 0.f;
    __syncthreads();
    for (int idx = tid; idx < 784; idx += 256) {
        int i = idx / 28, j = idx % 28;
        xs[(i + 1) * 30 + (j + 1)] = x[b * 784 + idx];
    }
    Us[tid] = U[tid];
    if (tid < 9)  dws[tid] = dw_w[tid];
    if (tid < 32) { pwws[tid] = pw_w[tid]; pwbs[tid] = pw_b[tid]; }
    __syncthreads();

    if (tid < 196) {
        const int i = tid / 14, j = tid % 14;
        float* fb = g_fmap + b * 7056;

        // ---- depthwise conv3x3 (pad 1) -> 2x2 avgpool, then 32-ch affine ----
        float ysum = 0.f;
        #pragma unroll
        for (int dy = 0; dy < 2; dy++)
            #pragma unroll
            for (int dx = 0; dx < 2; dx++) {
                const int oy = 2 * i + dy, ox = 2 * j + dx;
                #pragma unroll
                for (int ky = 0; ky < 3; ky++)
                    #pragma unroll
                    for (int kx = 0; kx < 3; kx++)
                        ysum += dws[ky * 3 + kx] * xs[(oy + ky) * 30 + (ox + kx)];
            }
        const float yp = 0.25f * ysum;
        #pragma unroll 8
        for (int c = 0; c < 32; c++)
            fb[c * 196 + tid] = pwws[c] * yp + pwbs[c];

        // ---- quantum patch: RY product state -> U -> PauliZ expectations ----
        float a[4][2];
        #pragma unroll
        for (int k = 0; k < 4; k++) {
            const float p = xs[(1 + 2 * i + (k >> 1)) * 30 + (1 + 2 * j + (k & 1))];
            float s, c2;
            sincosf(0.5f * p, &s, &c2);
            a[k][0] = c2; a[k][1] = s;
        }
        float t2[4];
        #pragma unroll
        for (int m = 0; m < 4; m++) t2[m] = a[0][m >> 1] * a[1][m & 1];
        float amp[16];
        #pragma unroll
        for (int m = 0; m < 16; m++)
            amp[m] = t2[m >> 2] * a[2][(m >> 1) & 1] * a[3][m & 1];

        float meas[4] = {0.f, 0.f, 0.f, 0.f};
        #pragma unroll
        for (int n = 0; n < 16; n++) {
            float st = 0.f;
            #pragma unroll
            for (int m = 0; m < 16; m++) st += Us[n * 16 + m] * amp[m];
            const float sq = st * st;
            #pragma unroll
            for (int w = 0; w < 4; w++)
                meas[w] += ((n >> (3 - w)) & 1) ? -sq : sq;
        }
        // channel scramble: flat k over (14,14,4) -> (c = 32 + k/196, s = k%196)
        #pragma unroll
        for (int w = 0; w < 4; w++) {
            const int k = tid * 4 + w;
            fb[(32 + k / 196) * 196 + (k % 196)] = meas[w];
        }
    }
}

// ---------------------------------------------------------------------------
// Kernel B: fus conv 36->128 (3x3, pad 1) + bias + ReLU + 2x2 avgpool
// block = (channel group of 32, sample). 196 threads = 49 pooled quads x 4.
// Each thread: 8 channels x (2x2 conv outputs) register tile = 32 accumulators.
// ---------------------------------------------------------------------------
__global__ __launch_bounds__(196, 2) void fusB(
    const float* __restrict__ fus_w,  // (128,36,3,3)
    const float* __restrict__ fus_b)  // (128)
{
    extern __shared__ float sm[];
    float* in_s = sm;                 // 36 planes of 16x16 (zero-padded)
    float* w_s  = sm + 36 * 256;      // 32 channels x 324 weights

    const int group = blockIdx.x;     // 0..3
    const int b     = blockIdx.y;
    const int tid   = threadIdx.x;
    const float* fb = g_fmap + b * 7056;

    for (int idx = tid; idx < 36 * 256; idx += 196) in_s[idx] = 0.f;
    __syncthreads();
    for (int idx = tid; idx < 7056; idx += 196) {
        const int ci = idx / 196, s = idx % 196;
        const int i = s / 14, j = s % 14;
        in_s[ci * 256 + (i + 1) * 16 + (j + 1)] = fb[idx];
    }
    for (int idx = tid; idx < 32 * 324; idx += 196)
        w_s[idx] = fus_w[group * 32 * 324 + idx];
    __syncthreads();

    const int q = tid % 49, gg = tid / 49;     // quad, channel sub-group
    const int pi = q / 7, pj = q % 7;

    float acc[8][4];
    #pragma unroll
    for (int rc = 0; rc < 8; rc++) {
        const int cl = (rc >> 2) * 16 + gg * 4 + (rc & 3);
        const float bias = __ldg(&fus_b[group * 32 + cl]);
        acc[rc][0] = bias; acc[rc][1] = bias; acc[rc][2] = bias; acc[rc][3] = bias;
    }

    for (int ci = 0; ci < 36; ci++) {
        float in[4][4];
        const int base = ci * 256 + (2 * pi) * 16 + 2 * pj;
        #pragma unroll
        for (int r = 0; r < 4; r++)
            #pragma unroll
            for (int c = 0; c < 4; c++)
                in[r][c] = in_s[base + r * 16 + c];

        #pragma unroll
        for (int rc = 0; rc < 8; rc++) {
            const int cl = (rc >> 2) * 16 + gg * 4 + (rc & 3);
            const float* wp = w_s + cl * 324 + ci * 9;
            const float w0 = wp[0], w1 = wp[1], w2 = wp[2];
            const float w3 = wp[3], w4 = wp[4], w5 = wp[5];
            const float w6 = wp[6], w7 = wp[7], w8 = wp[8];
            #pragma unroll
            for (int dy = 0; dy < 2; dy++)
                #pragma unroll
                for (int dx = 0; dx < 2; dx++) {
                    float v = acc[rc][dy * 2 + dx];
                    v += w0 * in[dy + 0][dx + 0];
                    v += w1 * in[dy + 0][dx + 1];
                    v += w2 * in[dy + 0][dx + 2];
                    v += w3 * in[dy + 1][dx + 0];
                    v += w4 * in[dy + 1][dx + 1];
                    v += w5 * in[dy + 1][dx + 2];
                    v += w6 * in[dy + 2][dx + 0];
                    v += w7 * in[dy + 2][dx + 1];
                    v += w8 * in[dy + 2][dx + 2];
                    acc[rc][dy * 2 + dx] = v;
                }
        }
    }

    float* pp = g_pool + b * 6272 + group * 32 * 49;
    #pragma unroll
    for (int rc = 0; rc < 8; rc++) {
        const int cl = (rc >> 2) * 16 + gg * 4 + (rc & 3);
        const float p0 = fmaxf(acc[rc][0], 0.f);
        const float p1 = fmaxf(acc[rc][1], 0.f);
        const float p2 = fmaxf(acc[rc][2], 0.f);
        const float p3 = fmaxf(acc[rc][3], 0.f);
        pp[cl * 49 + pi * 7 + pj] = 0.25f * (p0 + p1 + p2 + p3);
    }
}

// ---------------------------------------------------------------------------
// Kernel C: classifier. 11 warps per block; warp w = dot(flat, row_w).
// Output layout: [logits (1024x10) | aux (1024)]  as one float buffer.
// ---------------------------------------------------------------------------
__global__ __launch_bounds__(352) void clsC(
    const float* __restrict__ cls_w,  // (10, 6272)
    const float* __restrict__ cls_b,  // (10)
    const float* __restrict__ reg_w,  // (1, 6272)
    const float* __restrict__ reg_b,  // (1)
    float* __restrict__ out)
{
    const int b = blockIdx.x;
    const int w = threadIdx.x >> 5, lane = threadIdx.x & 31;
    const float* flat = g_pool + b * 6272;
    const float* wr = (w < 10) ? (cls_w + w * 6272) : reg_w;

    float acc = 0.f;
    for (int idx = lane; idx < 6272; idx += 32)
        acc += flat[idx] * wr[idx];
    #pragma unroll
    for (int off = 16; off; off >>= 1)
        acc += __shfl_xor_sync(0xffffffffu, acc, off);
    if (lane == 0) {
        if (w < 10) out[b * 10 + w] = acc + cls_b[0 + w];
        else        out[NB * 10 + b] = acc + reg_b[0];
    }
}

// ---------------------------------------------------------------------------
extern "C" void kernel_launch(void* const* d_in, const int* in_sizes, int n_in,
                              void* d_out, int out_size)
{
    const float* x     = (const float*)d_in[0];
    const float* dw_w  = (const float*)d_in[1];
    const float* pw_w  = (const float*)d_in[2];
    const float* pw_b  = (const float*)d_in[3];
    const float* U     = (const float*)d_in[4];
    const float* fus_w = (const float*)d_in[5];
    const float* fus_b = (const float*)d_in[6];
    const float* cls_w = (const float*)d_in[7];
    const float* cls_b = (const float*)d_in[8];
    const float* reg_w = (const float*)d_in[9];
    const float* reg_b = (const float*)d_in[10];
    float* out = (float*)d_out;

    const int smemB = (36 * 256 + 32 * 324) * (int)sizeof(float);  // 78336 B
    cudaFuncSetAttribute(fusB, cudaFuncAttributeMaxDynamicSharedMemorySize, smemB);

    featA<<<NB, 256>>>(x, dw_w, pw_w, pw_b, U);
    fusB<<<dim3(4, NB), 196, smemB>>>(fus_w, fus_b);
    clsC<<<NB, 352>>>(cls_w, cls_b, reg_w, reg_b, out);
}

// round 9
// speedup vs baseline: 1.1350x; 1.1350x over previous
#include <cuda_runtime.h>
#include <math.h>

// ---------------------------------------------------------------------------
// QuanvolutionEnhanced — fp32 SIMT implementation, 3 kernels.
//   A: per-sample 36-channel 14x14 feature map (ds-conv pooled + quantum patches)
//   B: 36->128 3x3 conv + bias + ReLU + 2x2 avgpool — now packed fma.rn.f32x2
//   C: classifier heads (10 logits + 1 aux) via warp-per-row dot products
// ---------------------------------------------------------------------------

#define NB 1024

__device__ float g_fmap[NB * 36 * 196];   // (b, c, 14*14)
__device__ float g_pool[NB * 128 * 49];   // (b, c, 7*7)  == flattened features

// ---- packed f32x2 helpers (sm_100+ PTX; FFMA2 is not emitted by ptxas) -----
__device__ __forceinline__ unsigned long long pack2(float lo, float hi) {
    unsigned long long r;
    asm("mov.b64 %0, {%1, %2};" : "=l"(r) : "f"(lo), "f"(hi));
    return r;
}
__device__ __forceinline__ void fma2(unsigned long long& d,
                                     unsigned long long a,
                                     unsigned long long b) {
    asm("fma.rn.f32x2 %0, %1, %2, %0;" : "+l"(d) : "l"(a), "l"(b));
}
__device__ __forceinline__ void unpack2(float& lo, float& hi, unsigned long long v) {
    asm("mov.b64 {%0, %1}, %2;" : "=f"(lo), "=f"(hi) : "l"(v));
}

// ---------------------------------------------------------------------------
// Kernel A
// ---------------------------------------------------------------------------
__global__ __launch_bounds__(256) void featA(
    const float* __restrict__ x,     // (B,1,28,28)
    const float* __restrict__ dw_w,  // (1,1,3,3)
    const float* __restrict__ pw_w,  // (32,1,1,1)
    const float* __restrict__ pw_b,  // (32)
    const float* __restrict__ U)     // (16,16)
{
    __shared__ float xs[30 * 30];    // zero-padded input
    __shared__ float Us[256];
    __shared__ float dws[9];
    __shared__ float pwws[32], pwbs[32];

    const int b = blockIdx.x;
    const int tid = threadIdx.x;

    for (int idx = tid; idx < 900; idx += 256) xs[idx] = 0.f;
    __syncthreads();
    for (int idx = tid; idx < 784; idx += 256) {
        int i = idx / 28, j = idx % 28;
        xs[(i + 1) * 30 + (j + 1)] = x[b * 784 + idx];
    }
    Us[tid] = U[tid];
    if (tid < 9)  dws[tid] = dw_w[tid];
    if (tid < 32) { pwws[tid] = pw_w[tid]; pwbs[tid] = pw_b[tid]; }
    __syncthreads();

    if (tid < 196) {
        const int i = tid / 14, j = tid % 14;
        float* fb = g_fmap + b * 7056;

        // ---- depthwise conv3x3 (pad 1) -> 2x2 avgpool, then 32-ch affine ----
        float ysum = 0.f;
        #pragma unroll
        for (int dy = 0; dy < 2; dy++)
            #pragma unroll
            for (int dx = 0; dx < 2; dx++) {
                const int oy = 2 * i + dy, ox = 2 * j + dx;
                #pragma unroll
                for (int ky = 0; ky < 3; ky++)
                    #pragma unroll
                    for (int kx = 0; kx < 3; kx++)
                        ysum += dws[ky * 3 + kx] * xs[(oy + ky) * 30 + (ox + kx)];
            }
        const float yp = 0.25f * ysum;
        #pragma unroll 8
        for (int c = 0; c < 32; c++)
            fb[c * 196 + tid] = pwws[c] * yp + pwbs[c];

        // ---- quantum patch: RY product state -> U -> PauliZ expectations ----
        float a[4][2];
        #pragma unroll
        for (int k = 0; k < 4; k++) {
            const float p = xs[(1 + 2 * i + (k >> 1)) * 30 + (1 + 2 * j + (k & 1))];
            float s, c2;
            sincosf(0.5f * p, &s, &c2);
            a[k][0] = c2; a[k][1] = s;
        }
        float t2[4];
        #pragma unroll
        for (int m = 0; m < 4; m++) t2[m] = a[0][m >> 1] * a[1][m & 1];
        float amp[16];
        #pragma unroll
        for (int m = 0; m < 16; m++)
            amp[m] = t2[m >> 2] * a[2][(m >> 1) & 1] * a[3][m & 1];

        float meas[4] = {0.f, 0.f, 0.f, 0.f};
        #pragma unroll
        for (int n = 0; n < 16; n++) {
            float st = 0.f;
            #pragma unroll
            for (int m = 0; m < 16; m++) st += Us[n * 16 + m] * amp[m];
            const float sq = st * st;
            #pragma unroll
            for (int w = 0; w < 4; w++)
                meas[w] += ((n >> (3 - w)) & 1) ? -sq : sq;
        }
        // channel scramble: flat k over (14,14,4) -> (c = 32 + k/196, s = k%196)
        #pragma unroll
        for (int w = 0; w < 4; w++) {
            const int k = tid * 4 + w;
            fb[(32 + k / 196) * 196 + (k % 196)] = meas[w];
        }
    }
}

// ---------------------------------------------------------------------------
// Kernel B: fus conv 36->128 (3x3, pad 1) + bias + ReLU + 2x2 avgpool
// block = (channel group of 32, sample). 196 threads = 49 pooled quads x 4.
// Packed f32x2: each thread owns 4 CHANNEL-PAIRS x (2x2 conv outputs)
// = 16 packed accumulators = 32 fp32 outputs. Weights pre-interleaved in
// smem so one LDS.64 yields the packed {w_c, w_c+1} operand directly.
// ---------------------------------------------------------------------------
__global__ __launch_bounds__(196, 2) void fusB(
    const float* __restrict__ fus_w,  // (128,36,3,3)
    const float* __restrict__ fus_b)  // (128)
{
    extern __shared__ float sm[];
    float*  in_s = sm;                        // 36 planes of 16x16 (zero-padded)
    float2* w_s2 = (float2*)(sm + 36 * 256);  // 16 channel-pairs x 324 packed w

    const int group = blockIdx.x;     // 0..3
    const int b     = blockIdx.y;
    const int tid   = threadIdx.x;
    const float* fb = g_fmap + b * 7056;

    for (int idx = tid; idx < 36 * 256; idx += 196) in_s[idx] = 0.f;
    __syncthreads();
    for (int idx = tid; idx < 7056; idx += 196) {
        const int ci = idx / 196, s = idx % 196;
        const int i = s / 14, j = s % 14;
        in_s[ci * 256 + (i + 1) * 16 + (j + 1)] = fb[idx];
    }
    // interleave weights by channel pair: w_s2[p*324 + k] = {w[2p][k], w[2p+1][k]}
    for (int idx = tid; idx < 32 * 324; idx += 196) {
        const int c = idx / 324, k = idx % 324;
        ((float*)w_s2)[(c >> 1) * 648 + k * 2 + (c & 1)] =
            fus_w[group * 32 * 324 + idx];
    }
    __syncthreads();

    const int q = tid % 49, gg = tid / 49;     // pooled quad, channel sub-group
    const int pi = q / 7, pj = q % 7;

    unsigned long long acc[4][4];              // [pair][2x2 spatial]
    #pragma unroll
    for (int pr = 0; pr < 4; pr++) {
        const int p = (pr >> 1) * 8 + gg * 2 + (pr & 1);  // pair index 0..15
        const unsigned long long bb =
            pack2(__ldg(&fus_b[group * 32 + 2 * p]),
                  __ldg(&fus_b[group * 32 + 2 * p + 1]));
        acc[pr][0] = bb; acc[pr][1] = bb; acc[pr][2] = bb; acc[pr][3] = bb;
    }

    for (int ci = 0; ci < 36; ci++) {
        const int base = ci * 256 + (2 * pi) * 16 + 2 * pj;
        unsigned long long in2[4][4];          // broadcast pairs {v,v}
        #pragma unroll
        for (int r = 0; r < 4; r++) {
            const float2 v0 = *(const float2*)(in_s + base + r * 16);
            const float2 v1 = *(const float2*)(in_s + base + r * 16 + 2);
            in2[r][0] = pack2(v0.x, v0.x);
            in2[r][1] = pack2(v0.y, v0.y);
            in2[r][2] = pack2(v1.x, v1.x);
            in2[r][3] = pack2(v1.y, v1.y);
        }

        #pragma unroll
        for (int pr = 0; pr < 4; pr++) {
            const int p = (pr >> 1) * 8 + gg * 2 + (pr & 1);
            const float2* wp = w_s2 + p * 324 + ci * 9;
            unsigned long long w[9];
            #pragma unroll
            for (int k = 0; k < 9; k++)
                w[k] = *(const unsigned long long*)(wp + k);
            #pragma unroll
            for (int dy = 0; dy < 2; dy++)
                #pragma unroll
                for (int dx = 0; dx < 2; dx++) {
                    #pragma unroll
                    for (int ky = 0; ky < 3; ky++)
                        #pragma unroll
                        for (int kx = 0; kx < 3; kx++)
                            fma2(acc[pr][dy * 2 + dx],
                                 w[ky * 3 + kx], in2[dy + ky][dx + kx]);
                }
        }
    }

    float* pp = g_pool + b * 6272 + group * 32 * 49;
    #pragma unroll
    for (int pr = 0; pr < 4; pr++) {
        const int p = (pr >> 1) * 8 + gg * 2 + (pr & 1);
        float lo[4], hi[4];
        #pragma unroll
        for (int t = 0; t < 4; t++) unpack2(lo[t], hi[t], acc[pr][t]);
        const float s0 = fmaxf(lo[0], 0.f) + fmaxf(lo[1], 0.f)
                       + fmaxf(lo[2], 0.f) + fmaxf(lo[3], 0.f);
        const float s1 = fmaxf(hi[0], 0.f) + fmaxf(hi[1], 0.f)
                       + fmaxf(hi[2], 0.f) + fmaxf(hi[3], 0.f);
        pp[(2 * p) * 49 + pi * 7 + pj]     = 0.25f * s0;
        pp[(2 * p + 1) * 49 + pi * 7 + pj] = 0.25f * s1;
    }
}

// ---------------------------------------------------------------------------
// Kernel C: classifier. 11 warps per block; warp w = dot(flat, row_w).
// Output layout: [logits (1024x10) | aux (1024)]  as one float buffer.
// ---------------------------------------------------------------------------
__global__ __launch_bounds__(352) void clsC(
    const float* __restrict__ cls_w,  // (10, 6272)
    const float* __restrict__ cls_b,  // (10)
    const float* __restrict__ reg_w,  // (1, 6272)
    const float* __restrict__ reg_b,  // (1)
    float* __restrict__ out)
{
    const int b = blockIdx.x;
    const int w = threadIdx.x >> 5, lane = threadIdx.x & 31;
    const float* flat = g_pool + b * 6272;
    const float* wr = (w < 10) ? (cls_w + w * 6272) : reg_w;

    float acc = 0.f;
    for (int idx = lane; idx < 6272; idx += 32)
        acc += flat[idx] * wr[idx];
    #pragma unroll
    for (int off = 16; off; off >>= 1)
        acc += __shfl_xor_sync(0xffffffffu, acc, off);
    if (lane == 0) {
        if (w < 10) out[b * 10 + w] = acc + cls_b[0 + w];
        else        out[NB * 10 + b] = acc + reg_b[0];
    }
}

// ---------------------------------------------------------------------------
extern "C" void kernel_launch(void* const* d_in, const int* in_sizes, int n_in,
                              void* d_out, int out_size)
{
    const float* x     = (const float*)d_in[0];
    const float* dw_w  = (const float*)d_in[1];
    const float* pw_w  = (const float*)d_in[2];
    const float* pw_b  = (const float*)d_in[3];
    const float* U     = (const float*)d_in[4];
    const float* fus_w = (const float*)d_in[5];
    const float* fus_b = (const float*)d_in[6];
    const float* cls_w = (const float*)d_in[7];
    const float* cls_b = (const float*)d_in[8];
    const float* reg_w = (const float*)d_in[9];
    const float* reg_b = (const float*)d_in[10];
    float* out = (float*)d_out;

    const int smemB = (36 * 256 + 32 * 324) * (int)sizeof(float);  // 78336 B
    cudaFuncSetAttribute(fusB, cudaFuncAttributeMaxDynamicSharedMemorySize, smemB);

    featA<<<NB, 256>>>(x, dw_w, pw_w, pw_b, U);
    fusB<<<dim3(4, NB), 196, smemB>>>(fus_w, fus_b);
    clsC<<<NB, 352>>>(cls_w, cls_b, reg_w, reg_b, out);
}

// round 12
// speedup vs baseline: 1.4422x; 1.2706x over previous
#include <cuda_runtime.h>
#include <cuda_bf16.h>
#include <math.h>
#include <stdint.h>

// ---------------------------------------------------------------------------
// QuanvolutionEnhanced — warp-mma (HMMA bf16x3) implicit-GEMM version.
//   prepW: split fus_w into bf16 hi/lo chunk images (once, ldmatrix layout)
//   featA: per-sample 36-ch 14x14 feature map (ds-conv pooled + quantum)
//   fusB : per-sample GEMM D[128,208] = W[128,336] * Xcol[336,208] via
//          mma.sync.m16n8k16 bf16, 3 split passes (hi*hi+hi*lo+lo*hi),
//          fused bias+ReLU+2x2 avgpool epilogue (shfl pooling)
//   clsC : classifier heads
// ---------------------------------------------------------------------------

#define NB 1024
#define NPAD 208            // 13 n16 tiles; cols = quad*4 + dy*2 + dx (49 quads valid)
#define NCHUNK 6            // K chunks of 64 (324 valid of 384; chunk5 uses 1 kstep)

// SMEM byte offsets (rows strided 144 B = 36 u32 for conflict-free ldmatrix)
#define SMO_INS  0          // 36 planes 16x16 fp32            (36864 B)
#define SMO_AHI  36864      // A chunk hi: 128 rows x 144 B    (18432 B)
#define SMO_ALO  55296
#define SMO_BHI  73728      // B chunk hi: 208 rows x 144 B    (29952 B)
#define SMO_BLO  103680
#define SMEM_B_TOTAL 133632
#define AOFF 18432
#define BOFF 29952

__device__ float g_fmap[NB * 36 * 196];     // (b, c, 14*14)
__device__ float g_pool[NB * 128 * 49];     // (b, c, 7*7)
__device__ uint32_t gAhi[NCHUNK * 128 * 36];// per-chunk 128 rows x 36 u32 (32 valid)
__device__ uint32_t gAlo[NCHUNK * 128 * 36];

// ---------------------------------------------------------------------------
__device__ __forceinline__ uint32_t smem_u32(const void* p) {
    uint32_t a;
    asm("{ .reg .u64 t; cvta.to.shared.u64 t, %1; cvt.u32.u64 %0, t; }"
        : "=r"(a) : "l"(p));
    return a;
}
__device__ __forceinline__ void split_bf16(float v, uint32_t& hp, uint32_t& lp,
                                           int e) {
    __nv_bfloat16 h = __float2bfloat16(v);
    __nv_bfloat16 l = __float2bfloat16(v - __bfloat162float(h));
    hp |= (uint32_t)__bfloat16_as_ushort(h) << (16 * e);
    lp |= (uint32_t)__bfloat16_as_ushort(l) << (16 * e);
}
__device__ __forceinline__ void ldsm4(uint32_t* r, uint32_t addr) {
    asm volatile("ldmatrix.sync.aligned.m8n8.x4.shared.b16 {%0,%1,%2,%3}, [%4];"
                 : "=r"(r[0]), "=r"(r[1]), "=r"(r[2]), "=r"(r[3]) : "r"(addr));
}
__device__ __forceinline__ void mma16816(float* d, const uint32_t* a,
                                         const uint32_t* b) {
    asm volatile(
        "mma.sync.aligned.m16n8k16.row.col.f32.bf16.bf16.f32 "
        "{%0,%1,%2,%3}, {%4,%5,%6,%7}, {%8,%9}, {%0,%1,%2,%3};"
        : "+f"(d[0]), "+f"(d[1]), "+f"(d[2]), "+f"(d[3])
        : "r"(a[0]), "r"(a[1]), "r"(a[2]), "r"(a[3]), "r"(b[0]), "r"(b[1]));
}

// ---------------------------------------------------------------------------
// prepW: bf16 hi/lo split of fus_w into per-chunk [row][k] images (once).
// ---------------------------------------------------------------------------
__global__ __launch_bounds__(256) void prepW(const float* __restrict__ fus_w) {
    const int idx = blockIdx.x * 256 + threadIdx.x;
    if (idx >= 128 * 192) return;
    const int c = idx / 192, kp = idx % 192;
    uint32_t hp = 0, lp = 0;
    #pragma unroll
    for (int e = 0; e < 2; e++) {
        const int k = 2 * kp + e;
        const float v = (k < 324) ? fus_w[c * 324 + k] : 0.f;
        split_bf16(v, hp, lp, e);
    }
    const int chunk = kp >> 5, kpin = kp & 31;
    gAhi[chunk * 4608 + c * 36 + kpin] = hp;
    gAlo[chunk * 4608 + c * 36 + kpin] = lp;
}

// ---------------------------------------------------------------------------
// Kernel A (unchanged)
// ---------------------------------------------------------------------------
__global__ __launch_bounds__(256) void featA(
    const float* __restrict__ x, const float* __restrict__ dw_w,
    const float* __restrict__ pw_w, const float* __restrict__ pw_b,
    const float* __restrict__ U)
{
    __shared__ float xs[30 * 30];
    __shared__ float Us[256];
    __shared__ float dws[9];
    __shared__ float pwws[32], pwbs[32];

    const int b = blockIdx.x;
    const int tid = threadIdx.x;

    for (int idx = tid; idx < 900; idx += 256) xs[idx] = 0.f;
    __syncthreads();
    for (int idx = tid; idx < 784; idx += 256) {
        int i = idx / 28, j = idx % 28;
        xs[(i + 1) * 30 + (j + 1)] = x[b * 784 + idx];
    }
    Us[tid] = U[tid];
    if (tid < 9)  dws[tid] = dw_w[tid];
    if (tid < 32) { pwws[tid] = pw_w[tid]; pwbs[tid] = pw_b[tid]; }
    __syncthreads();

    if (tid < 196) {
        const int i = tid / 14, j = tid % 14;
        float* fb = g_fmap + b * 7056;

        float ysum = 0.f;
        #pragma unroll
        for (int dy = 0; dy < 2; dy++)
            #pragma unroll
            for (int dx = 0; dx < 2; dx++) {
                const int oy = 2 * i + dy, ox = 2 * j + dx;
                #pragma unroll
                for (int ky = 0; ky < 3; ky++)
                    #pragma unroll
                    for (int kx = 0; kx < 3; kx++)
                        ysum += dws[ky * 3 + kx] * xs[(oy + ky) * 30 + (ox + kx)];
            }
        const float yp = 0.25f * ysum;
        #pragma unroll 8
        for (int c = 0; c < 32; c++)
            fb[c * 196 + tid] = pwws[c] * yp + pwbs[c];

        float a[4][2];
        #pragma unroll
        for (int k = 0; k < 4; k++) {
            const float p = xs[(1 + 2 * i + (k >> 1)) * 30 + (1 + 2 * j + (k & 1))];
            float s, c2;
            sincosf(0.5f * p, &s, &c2);
            a[k][0] = c2; a[k][1] = s;
        }
        float t2[4];
        #pragma unroll
        for (int m = 0; m < 4; m++) t2[m] = a[0][m >> 1] * a[1][m & 1];
        float amp[16];
        #pragma unroll
        for (int m = 0; m < 16; m++)
            amp[m] = t2[m >> 2] * a[2][(m >> 1) & 1] * a[3][m & 1];

        float meas[4] = {0.f, 0.f, 0.f, 0.f};
        #pragma unroll
        for (int n = 0; n < 16; n++) {
            float st = 0.f;
            #pragma unroll
            for (int m = 0; m < 16; m++) st += Us[n * 16 + m] * amp[m];
            const float sq = st * st;
            #pragma unroll
            for (int w = 0; w < 4; w++)
                meas[w] += ((n >> (3 - w)) & 1) ? -sq : sq;
        }
        #pragma unroll
        for (int w = 0; w < 4; w++) {
            const int k = tid * 4 + w;
            fb[(32 + k / 196) * 196 + (k % 196)] = meas[w];
        }
    }
}

// ---------------------------------------------------------------------------
// Kernel B: warp-mma implicit GEMM. One CTA per sample, 256 threads = 8 warps.
// Warp w owns output rows 16w..16w+15 x all 208 cols (104 fp32 accumulators).
// ---------------------------------------------------------------------------
__global__ __launch_bounds__(256, 1) void fusB(const float* __restrict__ fus_b)
{
    extern __shared__ __align__(128) char sm[];
    const uint32_t smb = smem_u32(sm);
    const int b = blockIdx.x;
    const int tid = threadIdx.x;
    const int wid = tid >> 5, lane = tid & 31;

    float* in_s = (float*)(sm + SMO_INS);

    for (int i = tid; i < 36 * 256; i += 256) in_s[i] = 0.f;
    __syncthreads();
    const float* fb = g_fmap + b * 7056;
    for (int i = tid; i < 7056; i += 256) {
        const int ci = i / 196, s = i % 196;
        in_s[ci * 256 + (s / 14 + 1) * 16 + (s % 14 + 1)] = fb[i];
    }

    // per-thread ldmatrix base addresses (mat = lane>>3)
    const int amat = lane >> 3, arow = lane & 7;
    const uint32_t aBase = smb + SMO_AHI
        + (16 * wid + ((amat & 1) << 3) + arow) * 144 + ((amat >> 1) << 4);
    const uint32_t bBase = smb + SMO_BHI
        + (((amat >> 1) << 3) + arow) * 144 + ((amat & 1) << 4);

    float acc[13][2][4];
    #pragma unroll
    for (int nt = 0; nt < 13; nt++)
        #pragma unroll
        for (int s2 = 0; s2 < 2; s2++)
            #pragma unroll
            for (int e = 0; e < 4; e++) acc[nt][s2][e] = 0.f;

    for (int chunk = 0; chunk < NCHUNK; chunk++) {
        __syncthreads();   // previous chunk's MMA reads done

        // stage A chunk (pre-split, ldmatrix layout)
        {
            const uint4* shp = (const uint4*)(gAhi + chunk * 4608);
            const uint4* slp = (const uint4*)(gAlo + chunk * 4608);
            uint4* dh = (uint4*)(sm + SMO_AHI);
            uint4* dl = (uint4*)(sm + SMO_ALO);
            #pragma unroll
            for (int i = tid; i < 1152; i += 256) { dh[i] = shp[i]; dl[i] = slp[i]; }
        }
        // build B chunk: 208 rows (n = quad*4 + dy*2 + dx) x 32 u32 (64 bf16 k)
        for (int idx = tid; idx < NPAD * 32; idx += 256) {
            const int n = idx >> 5, kp = idx & 31;
            const int q = n >> 2, dd = n & 3, dy = dd >> 1, dx = dd & 1;
            uint32_t hp = 0, lp = 0;
            if (q < 49) {
                const int pi = q / 7, pj = q % 7;
                #pragma unroll
                for (int e = 0; e < 2; e++) {
                    const int kg = chunk * 64 + 2 * kp + e;
                    float v = 0.f;
                    if (kg < 324) {
                        const int ci = kg / 9, r = kg - ci * 9;
                        const int ky = r / 3, kx = r - ky * 3;
                        // pixel (2pi+dy+ky-1, 2pj+dx+kx-1) in padded 16x16 plane
                        v = in_s[ci * 256 + (2 * pi + dy + ky) * 16
                                          + (2 * pj + dx + kx)];
                    }
                    split_bf16(v, hp, lp, e);
                }
            }
            ((uint32_t*)(sm + SMO_BHI))[n * 36 + kp] = hp;
            ((uint32_t*)(sm + SMO_BLO))[n * 36 + kp] = lp;
        }
        __syncthreads();

        const int nks = (chunk == 5) ? 1 : 4;   // K valid only to 324
        for (int s = 0; s < nks; s++) {
            uint32_t ah[4], al[4];
            ldsm4(ah, aBase + s * 32);
            ldsm4(al, aBase + AOFF + s * 32);
            #pragma unroll
            for (int nt = 0; nt < 13; nt++) {
                uint32_t bh[4], bl[4];
                const uint32_t bo = bBase + nt * 2304 + s * 32;
                ldsm4(bh, bo);
                ldsm4(bl, bo + BOFF);
                mma16816(acc[nt][0], ah, bh);       // hi*hi
                mma16816(acc[nt][1], ah, bh + 2);
                mma16816(acc[nt][0], ah, bl);       // hi*lo
                mma16816(acc[nt][1], ah, bl + 2);
                mma16816(acc[nt][0], al, bh);       // lo*hi
                mma16816(acc[nt][1], al, bh + 2);
            }
        }
    }

    // --- epilogue: bias + ReLU + 2x2 pool (dy partner = lane^1) ---
    const int m0 = 16 * wid + (lane >> 2);
    const int m1 = m0 + 8;
    const float bias0 = __ldg(&fus_b[m0]);
    const float bias1 = __ldg(&fus_b[m1]);
    float* pp = g_pool + b * 6272;
    #pragma unroll
    for (int nt = 0; nt < 13; nt++)
        #pragma unroll
        for (int s2 = 0; s2 < 2; s2++) {
            const float* d = acc[nt][s2];
            float v0 = fmaxf(d[0] + bias0, 0.f) + fmaxf(d[1] + bias0, 0.f);
            float v1 = fmaxf(d[2] + bias1, 0.f) + fmaxf(d[3] + bias1, 0.f);
            v0 += __shfl_xor_sync(0xffffffffu, v0, 1);
            v1 += __shfl_xor_sync(0xffffffffu, v1, 1);
            if (!(lane & 1)) {
                const int q = nt * 4 + s2 * 2 + ((lane & 3) >> 1);
                if (q < 49) {
                    pp[m0 * 49 + q] = 0.25f * v0;
                    pp[m1 * 49 + q] = 0.25f * v1;
                }
            }
        }
}

// ---------------------------------------------------------------------------
// Kernel C (unchanged)
// ---------------------------------------------------------------------------
__global__ __launch_bounds__(352) void clsC(
    const float* __restrict__ cls_w, const float* __restrict__ cls_b,
    const float* __restrict__ reg_w, const float* __restrict__ reg_b,
    float* __restrict__ out)
{
    const int b = blockIdx.x;
    const int w = threadIdx.x >> 5, lane = threadIdx.x & 31;
    const float* flat = g_pool + b * 6272;
    const float* wr = (w < 10) ? (cls_w + w * 6272) : reg_w;

    float acc = 0.f;
    for (int idx = lane; idx < 6272; idx += 32)
        acc += flat[idx] * wr[idx];
    #pragma unroll
    for (int off = 16; off; off >>= 1)
        acc += __shfl_xor_sync(0xffffffffu, acc, off);
    if (lane == 0) {
        if (w < 10) out[b * 10 + w] = acc + cls_b[w];
        else        out[NB * 10 + b] = acc + reg_b[0];
    }
}

// ---------------------------------------------------------------------------
extern "C" void kernel_launch(void* const* d_in, const int* in_sizes, int n_in,
                              void* d_out, int out_size)
{
    const float* x     = (const float*)d_in[0];
    const float* dw_w  = (const float*)d_in[1];
    const float* pw_w  = (const float*)d_in[2];
    const float* pw_b  = (const float*)d_in[3];
    const float* U     = (const float*)d_in[4];
    const float* fus_w = (const float*)d_in[5];
    const float* fus_b = (const float*)d_in[6];
    const float* cls_w = (const float*)d_in[7];
    const float* cls_b = (const float*)d_in[8];
    const float* reg_w = (const float*)d_in[9];
    const float* reg_b = (const float*)d_in[10];
    float* out = (float*)d_out;

    cudaFuncSetAttribute(fusB, cudaFuncAttributeMaxDynamicSharedMemorySize,
                         SMEM_B_TOTAL);

    prepW<<<96, 256>>>(fus_w);
    featA<<<NB, 256>>>(x, dw_w, pw_w, pw_b, U);
    fusB<<<NB, 256, SMEM_B_TOTAL>>>(fus_b);
    clsC<<<NB, 352>>>(cls_w, cls_b, reg_w, reg_b, out);
}

// round 16
// speedup vs baseline: 1.7373x; 1.2046x over previous
#include <cuda_runtime.h>
#include <cuda_bf16.h>
#include <math.h>
#include <stdint.h>

// ---------------------------------------------------------------------------
// QuanvolutionEnhanced — warp-mma (HMMA bf16x3) implicit-GEMM, pipelined.
//   prepW: emit A (weights) as ready m16n8k16 fragments, bf16 hi/lo (once)
//   featA: per-sample 36-ch 14x14 fmap, stored PRE-SPLIT as u32 (hi|lo<<16)
//   fusB : per-sample D[128,208] = W[128,336] * Xcol[336,208]
//          16 warps, A-frags via LDG.128, B im2col double-buffered (PRMT pack),
//          single barrier/chunk, fused bias+ReLU+2x2 avgpool epilogue
//   clsC : classifier heads, 4 samples/block with smem-staged features
// ---------------------------------------------------------------------------

#define NB 1024
#define NPAD 208            // 13 n16 tiles; col n = quad*4 + dy*2 + dx
#define NCHUNK 6            // K chunks of 64 (324 valid)

// fusB smem offsets (B rows strided 144 B = 36 u32, conflict-free ldmatrix)
#define SMO_INS  0          // 36 planes 16x16 packed u32     (36864 B)
#define SMO_B0H  36864
#define SMO_B0L  66816
#define SMO_B1H  96768
#define SMO_B1L  126720
#define SMO_TAB  156672     // 384 u32 offset table
#define SMEM_B_TOTAL 158208
#define BLO_OFF  29952      // lo buffer offset from hi

#define SMEM_C_TOTAL (4 * 6272 * 4)   // clsC: 4 staged feature vectors

__device__ uint32_t g_fmapP[NB * 36 * 196]; // packed bf16 hi|lo<<16
__device__ float    g_pool[NB * 128 * 49];  // (b, c, 7*7)
__device__ uint4    gAfH[21 * 8 * 32];      // A frags hi: [ksg][stripe][lane]
__device__ uint4    gAfL[21 * 8 * 32];      // A frags lo

// ---------------------------------------------------------------------------
__device__ __forceinline__ uint32_t smem_u32(const void* p) {
    uint32_t a;
    asm("{ .reg .u64 t; cvta.to.shared.u64 t, %1; cvt.u32.u64 %0, t; }"
        : "=r"(a) : "l"(p));
    return a;
}
__device__ __forceinline__ uint32_t pack_split(float v) {
    __nv_bfloat16 h = __float2bfloat16(v);
    __nv_bfloat16 l = __float2bfloat16(v - __bfloat162float(h));
    return (uint32_t)__bfloat16_as_ushort(h)
         | ((uint32_t)__bfloat16_as_ushort(l) << 16);
}
__device__ __forceinline__ void ldsm4(uint32_t* r, uint32_t addr) {
    asm volatile("ldmatrix.sync.aligned.m8n8.x4.shared.b16 {%0,%1,%2,%3}, [%4];"
                 : "=r"(r[0]), "=r"(r[1]), "=r"(r[2]), "=r"(r[3]) : "r"(addr));
}
__device__ __forceinline__ void mma16816(float* d, const uint32_t* a,
                                         const uint32_t* b) {
    asm volatile(
        "mma.sync.aligned.m16n8k16.row.col.f32.bf16.bf16.f32 "
        "{%0,%1,%2,%3}, {%4,%5,%6,%7}, {%8,%9}, {%0,%1,%2,%3};"
        : "+f"(d[0]), "+f"(d[1]), "+f"(d[2]), "+f"(d[3])
        : "r"(a[0]), "r"(a[1]), "r"(a[2]), "r"(a[3]), "r"(b[0]), "r"(b[1]));
}

// ---------------------------------------------------------------------------
// prepW: A fragments. ksg = global kstep 0..20 (k = 16*ksg), 8 m-stripes,
// 32 lanes. Reg e: row = stripe*16 + (e&1)*8 + lane/4,
//                 k   = ksg*16 + (e>>1)*8 + (lane%4)*2 (+1)
// ---------------------------------------------------------------------------
__global__ __launch_bounds__(256) void prepW(const float* __restrict__ fus_w) {
    const int ksg = blockIdx.x;               // 0..20
    const int stripe = threadIdx.x >> 5, lane = threadIdx.x & 31;
    uint32_t hi[4], lo[4];
    #pragma unroll
    for (int e = 0; e < 4; e++) {
        const int row = stripe * 16 + ((e & 1) << 3) + (lane >> 2);
        const int k   = ksg * 16 + ((e >> 1) << 3) + (lane & 3) * 2;
        const float v0 = (k     < 324) ? fus_w[row * 324 + k]     : 0.f;
        const float v1 = (k + 1 < 324) ? fus_w[row * 324 + k + 1] : 0.f;
        const uint32_t p0 = pack_split(v0), p1 = pack_split(v1);
        hi[e] = __byte_perm(p0, p1, 0x5410);
        lo[e] = __byte_perm(p0, p1, 0x7632);
    }
    const int o = (ksg * 8 + stripe) * 32 + lane;
    gAfH[o] = make_uint4(hi[0], hi[1], hi[2], hi[3]);
    gAfL[o] = make_uint4(lo[0], lo[1], lo[2], lo[3]);
}

// ---------------------------------------------------------------------------
// Kernel A: fmap, written pre-split/packed.
// ---------------------------------------------------------------------------
__global__ __launch_bounds__(256) void featA(
    const float* __restrict__ x, const float* __restrict__ dw_w,
    const float* __restrict__ pw_w, const float* __restrict__ pw_b,
    const float* __restrict__ U)
{
    __shared__ float xs[30 * 30];
    __shared__ float Us[256];
    __shared__ float dws[9];
    __shared__ float pwws[32], pwbs[32];

    const int b = blockIdx.x;
    const int tid = threadIdx.x;

    for (int idx = tid; idx < 900; idx += 256) xs[idx] = 0.f;
    __syncthreads();
    for (int idx = tid; idx < 784; idx += 256) {
        int i = idx / 28, j = idx % 28;
        xs[(i + 1) * 30 + (j + 1)] = x[b * 784 + idx];
    }
    Us[tid] = U[tid];
    if (tid < 9)  dws[tid] = dw_w[tid];
    if (tid < 32) { pwws[tid] = pw_w[tid]; pwbs[tid] = pw_b[tid]; }
    __syncthreads();

    if (tid < 196) {
        const int i = tid / 14, j = tid % 14;
        uint32_t* fb = g_fmapP + b * 7056;

        float ysum = 0.f;
        #pragma unroll
        for (int dy = 0; dy < 2; dy++)
            #pragma unroll
            for (int dx = 0; dx < 2; dx++) {
                const int oy = 2 * i + dy, ox = 2 * j + dx;
                #pragma unroll
                for (int ky = 0; ky < 3; ky++)
                    #pragma unroll
                    for (int kx = 0; kx < 3; kx++)
                        ysum += dws[ky * 3 + kx] * xs[(oy + ky) * 30 + (ox + kx)];
            }
        const float yp = 0.25f * ysum;
        #pragma unroll 8
        for (int c = 0; c < 32; c++)
            fb[c * 196 + tid] = pack_split(pwws[c] * yp + pwbs[c]);

        float a[4][2];
        #pragma unroll
        for (int k = 0; k < 4; k++) {
            const float p = xs[(1 + 2 * i + (k >> 1)) * 30 + (1 + 2 * j + (k & 1))];
            float s, c2;
            sincosf(0.5f * p, &s, &c2);
            a[k][0] = c2; a[k][1] = s;
        }
        float t2[4];
        #pragma unroll
        for (int m = 0; m < 4; m++) t2[m] = a[0][m >> 1] * a[1][m & 1];
        float amp[16];
        #pragma unroll
        for (int m = 0; m < 16; m++)
            amp[m] = t2[m >> 2] * a[2][(m >> 1) & 1] * a[3][m & 1];

        float meas[4] = {0.f, 0.f, 0.f, 0.f};
        #pragma unroll
        for (int n = 0; n < 16; n++) {
            float st = 0.f;
            #pragma unroll
            for (int m = 0; m < 16; m++) st += Us[n * 16 + m] * amp[m];
            const float sq = st * st;
            #pragma unroll
            for (int w = 0; w < 4; w++)
                meas[w] += ((n >> (3 - w)) & 1) ? -sq : sq;
        }
        #pragma unroll
        for (int w = 0; w < 4; w++) {
            const int k = tid * 4 + w;
            fb[(32 + k / 196) * 196 + (k % 196)] = pack_split(meas[w]);
        }
    }
}

// ---------------------------------------------------------------------------
// Kernel B: 16 warps. warp = (m-stripe wid&7) x (N-half wid>>3).
// ---------------------------------------------------------------------------
__global__ __launch_bounds__(512, 1) void fusB(const float* __restrict__ fus_b)
{
    extern __shared__ __align__(128) char sm[];
    const uint32_t smb = smem_u32(sm);
    const int b = blockIdx.x;
    const int tid = threadIdx.x;
    const int wid = tid >> 5, lane = tid & 31;

    uint32_t* in_s  = (uint32_t*)(sm + SMO_INS);
    uint32_t* tab_s = (uint32_t*)(sm + SMO_TAB);

    for (int i = tid; i < 36 * 256; i += 512) in_s[i] = 0u;
    if (tid < 384) {
        const int kg = tid;
        const int ci = kg / 9, r = kg - ci * 9;
        tab_s[kg] = (kg < 324) ? (uint32_t)(ci * 256 + (r / 3) * 16 + (r % 3)) : 0u;
    }
    __syncthreads();
    const uint32_t* fb = g_fmapP + b * 7056;
    for (int i = tid; i < 7056; i += 512) {
        const int ci = i / 196, s = i % 196;
        in_s[ci * 256 + (s / 14 + 1) * 16 + (s % 14 + 1)] = fb[i];
    }
    __syncthreads();

    const int wm = wid & 7, wn = wid >> 3;
    const int nt0 = wn * 7;
    const int ntc = wn ? 6 : 7;
    // per-lane ldmatrix address part for B (row n, 144B stride)
    const uint32_t bLane = (((lane >> 4) << 3) + (lane & 7)) * 144
                         + (((lane >> 3) & 1) << 4);

    float acc[7][2][4];
    #pragma unroll
    for (int t = 0; t < 7; t++)
        #pragma unroll
        for (int s2 = 0; s2 < 2; s2++)
            #pragma unroll
            for (int e = 0; e < 4; e++) acc[t][s2][e] = 0.f;

    for (int chunk = 0; chunk < NCHUNK; chunk++) {
        uint32_t* bh = (uint32_t*)(sm + (chunk & 1 ? SMO_B1H : SMO_B0H));
        uint32_t* bl = (uint32_t*)(sm + (chunk & 1 ? SMO_B1L : SMO_B0L));

        // ---- build B chunk (PRMT repack of pre-split pixels) ----
        for (int idx = tid; idx < NPAD * 32; idx += 512) {
            const int n = idx >> 5, kp = idx & 31;
            uint32_t p0 = 0u, p1 = 0u;
            const int q = n >> 2;
            if (q < 49) {
                const int dd = n & 3;
                const int pi = q / 7, pj = q % 7;
                const int boff = (2 * pi + (dd >> 1)) * 16 + 2 * pj + (dd & 1);
                const int kg = chunk * 64 + 2 * kp;
                if (kg < 324)     p0 = in_s[tab_s[kg] + boff];
                if (kg + 1 < 324) p1 = in_s[tab_s[kg + 1] + boff];
            }
            bh[n * 36 + kp] = __byte_perm(p0, p1, 0x5410);
            bl[n * 36 + kp] = __byte_perm(p0, p1, 0x7632);
        }
        __syncthreads();   // single barrier: B[chunk] ready; buffers 2-deep

        // ---- MMA phase on this chunk ----
        const uint32_t bBase = smb + (chunk & 1 ? SMO_B1H : SMO_B0H) + bLane;
        const int nks = (chunk == 5) ? 1 : 4;
        for (int s = 0; s < nks; s++) {
            const int ksg = chunk * 4 + s;
            const uint4 h4 = __ldg(&gAfH[(ksg * 8 + wm) * 32 + lane]);
            const uint4 l4 = __ldg(&gAfL[(ksg * 8 + wm) * 32 + lane]);
            const uint32_t ah[4] = {h4.x, h4.y, h4.z, h4.w};
            const uint32_t al[4] = {l4.x, l4.y, l4.z, l4.w};
            #pragma unroll
            for (int t = 0; t < 7; t++) {
                if (t >= ntc) break;
                uint32_t bhf[4], blf[4];
                const uint32_t bo = bBase + (nt0 + t) * 2304 + s * 32;
                ldsm4(bhf, bo);
                ldsm4(blf, bo + BLO_OFF);
                mma16816(acc[t][0], ah, bhf);       // hi*hi
                mma16816(acc[t][1], ah, bhf + 2);
                mma16816(acc[t][0], ah, blf);       // hi*lo
                mma16816(acc[t][1], ah, blf + 2);
                mma16816(acc[t][0], al, bhf);       // lo*hi
                mma16816(acc[t][1], al, bhf + 2);
            }
        }
    }

    // ---- epilogue: bias + ReLU + 2x2 pool (dx partner = lane^1) ----
    const int m0 = 16 * wm + (lane >> 2);
    const int m1 = m0 + 8;
    const float bias0 = __ldg(&fus_b[m0]);
    const float bias1 = __ldg(&fus_b[m1]);
    float* pp = g_pool + b * 6272;
    #pragma unroll
    for (int t = 0; t < 7; t++) {
        if (t >= ntc) break;
        const int nt = nt0 + t;
        #pragma unroll
        for (int s2 = 0; s2 < 2; s2++) {
            const float* d = acc[t][s2];
            float v0 = fmaxf(d[0] + bias0, 0.f) + fmaxf(d[1] + bias0, 0.f);
            float v1 = fmaxf(d[2] + bias1, 0.f) + fmaxf(d[3] + bias1, 0.f);
            v0 += __shfl_xor_sync(0xffffffffu, v0, 1);
            v1 += __shfl_xor_sync(0xffffffffu, v1, 1);
            if (!(lane & 1)) {
                const int q = nt * 4 + s2 * 2 + ((lane & 3) >> 1);
                if (q < 49) {
                    pp[m0 * 49 + q] = 0.25f * v0;
                    pp[m1 * 49 + q] = 0.25f * v1;
                }
            }
        }
    }
}

// ---------------------------------------------------------------------------
// Kernel C: 4 samples per block, features staged in smem.
// ---------------------------------------------------------------------------
__global__ __launch_bounds__(352) void clsC(
    const float* __restrict__ cls_w, const float* __restrict__ cls_b,
    const float* __restrict__ reg_w, const float* __restrict__ reg_b,
    float* __restrict__ out)
{
    extern __shared__ float fl[];     // 4 x 6272
    const int b0 = blockIdx.x * 4;
    const int tid = threadIdx.x;
    const int w = tid >> 5, lane = tid & 31;

    const float* src = g_pool + b0 * 6272;
    for (int i = tid; i < 4 * 6272; i += 352) fl[i] = src[i];
    __syncthreads();

    const float* wr = (w < 10) ? (cls_w + w * 6272) : reg_w;
    float a0 = 0.f, a1 = 0.f, a2 = 0.f, a3 = 0.f;
    for (int idx = lane; idx < 6272; idx += 32) {
        const float wv = wr[idx];
        a0 += wv * fl[idx];
        a1 += wv * fl[6272 + idx];
        a2 += wv * fl[12544 + idx];
        a3 += wv * fl[18816 + idx];
    }
    #pragma unroll
    for (int off = 16; off; off >>= 1) {
        a0 += __shfl_xor_sync(0xffffffffu, a0, off);
        a1 += __shfl_xor_sync(0xffffffffu, a1, off);
        a2 += __shfl_xor_sync(0xffffffffu, a2, off);
        a3 += __shfl_xor_sync(0xffffffffu, a3, off);
    }
    if (lane == 0) {
        if (w < 10) {
            const float bb = cls_b[w];
            out[(b0 + 0) * 10 + w] = a0 + bb;
            out[(b0 + 1) * 10 + w] = a1 + bb;
            out[(b0 + 2) * 10 + w] = a2 + bb;
            out[(b0 + 3) * 10 + w] = a3 + bb;
        } else {
            const float bb = reg_b[0];
            out[NB * 10 + b0 + 0] = a0 + bb;
            out[NB * 10 + b0 + 1] = a1 + bb;
            out[NB * 10 + b0 + 2] = a2 + bb;
            out[NB * 10 + b0 + 3] = a3 + bb;
        }
    }
}

// ---------------------------------------------------------------------------
extern "C" void kernel_launch(void* const* d_in, const int* in_sizes, int n_in,
                              void* d_out, int out_size)
{
    const float* x     = (const float*)d_in[0];
    const float* dw_w  = (const float*)d_in[1];
    const float* pw_w  = (const float*)d_in[2];
    const float* pw_b  = (const float*)d_in[3];
    const float* U     = (const float*)d_in[4];
    const float* fus_w = (const float*)d_in[5];
    const float* fus_b = (const float*)d_in[6];
    const float* cls_w = (const float*)d_in[7];
    const float* cls_b = (const float*)d_in[8];
    const float* reg_w = (const float*)d_in[9];
    const float* reg_b = (const float*)d_in[10];
    float* out = (float*)d_out;

    cudaFuncSetAttribute(fusB, cudaFuncAttributeMaxDynamicSharedMemorySize,
                         SMEM_B_TOTAL);
    cudaFuncSetAttribute(clsC, cudaFuncAttributeMaxDynamicSharedMemorySize,
                         SMEM_C_TOTAL);

    prepW<<<21, 256>>>(fus_w);
    featA<<<NB, 256>>>(x, dw_w, pw_w, pw_b, U);
    fusB<<<NB, 512, SMEM_B_TOTAL>>>(fus_b);
    clsC<<<NB / 4, 352, SMEM_C_TOTAL>>>(cls_w, cls_b, reg_w, reg_b, out);
}